// round 15
// baseline (speedup 1.0000x reference)
#include <cuda_runtime.h>
#include <cuda_bf16.h>

#define NUM_G 32768
#define NREP  8      // accumulator replicas (cuts per-address red serialization)

// Scratch (allocation-free __device__ globals; zero-initialized at load).
// INVARIANT: all scratch is zero at kernel_launch entry; k_fin restores
// everything to zero, so every graph replay sees identical state.
__device__ float4   g_acc[NREP * NUM_G];  // {tsum, psum, S = sum exp(t)*p, count}
__device__ float    g_total;
__device__ int      g_nvalid;
__device__ unsigned g_done;

// Pure-FMA exp: exp(x) = 2^(x*log2e). Magic-number round, deg-5 poly on [-0.5,0.5].
__device__ __forceinline__ float fexp(float x) {
    const float L2E = 1.4426950408889634f;
    float z  = fmaf(x, L2E, 12582912.0f);
    int   n  = __float_as_int(z) - 0x4B400000;
    float zi = z - 12582912.0f;
    float f  = fmaf(x, L2E, -zi);
    float p  = 1.3333558146e-3f;
    p = fmaf(p, f, 9.6181291076e-3f);
    p = fmaf(p, f, 5.5504108664e-2f);
    p = fmaf(p, f, 2.4022650696e-1f);
    p = fmaf(p, f, 6.9314718056e-1f);
    p = fmaf(p, f, 1.0f);
    return __int_as_float(__float_as_int(p) + (n << 23));
}

// One 16-byte vectorized L2 reduction: {tsum += te, psum += pe, S += te*p, count += 1}
__device__ __forceinline__ void red4(float4* a, float te, float pe, float s) {
    asm volatile("red.global.add.v4.f32 [%0], {%1, %2, %3, %4};"
                 :: "l"(a), "f"(te), "f"(pe), "f"(s), "f"(1.0f) : "memory");
}

// Streaming float4 / int4 loads (evict-first).
__device__ __forceinline__ float4 ldcs4(const float4* p) {
    float4 v;
    asm volatile("ld.global.cs.v4.f32 {%0,%1,%2,%3}, [%4];"
                 : "=f"(v.x), "=f"(v.y), "=f"(v.z), "=f"(v.w) : "l"(p));
    return v;
}
__device__ __forceinline__ int4 ldcs4i(const int4* p) {
    int4 v;
    asm volatile("ld.global.cs.v4.b32 {%0,%1,%2,%3}, [%4];"
                 : "=r"(v.x), "=r"(v.y), "=r"(v.z), "=r"(v.w) : "l"(p));
    return v;
}

// One float4 chunk: 3 loads, 4 fexp, 4 red4 into this block's replica.
__device__ __forceinline__ void accum_chunk(const float4* __restrict__ p4,
                                            const float4* __restrict__ t4,
                                            const int4*  __restrict__ g4,
                                            float4* __restrict__ acc, int i) {
    float4 p = ldcs4(&p4[i]);
    float4 t = ldcs4(&t4[i]);
    int4   g = ldcs4i(&g4[i]);
    float ex = fexp(t.x), ey = fexp(t.y), ez = fexp(t.z), ew = fexp(t.w);
    red4(&acc[g.x], ex, fexp(p.x), ex * p.x);
    red4(&acc[g.y], ey, fexp(p.y), ey * p.y);
    red4(&acc[g.z], ez, fexp(p.z), ez * p.z);
    red4(&acc[g.w], ew, fexp(p.w), ew * p.w);
}

// Pass 1: per-group sums of exp(t), exp(p), exp(t)*p, count — ONE red.v4 per
// element, into one of NREP replicas (by blockIdx) to cut same-address
// serialization / slice hotspotting at the LTS atomic ALU.
__global__ void __launch_bounds__(256, 8) k_accum(const float4* __restrict__ p4,
                                                  const float4* __restrict__ t4,
                                                  const int4*  __restrict__ g4, int nv) {
    int half = nv >> 1;
    int i = blockIdx.x * blockDim.x + threadIdx.x;
    if (i >= half) return;
    float4* acc = g_acc + ((blockIdx.x & (NREP - 1)) << 15);   // replica base
    accum_chunk(p4, t4, g4, acc, i);
    accum_chunk(p4, t4, g4, acc, i + half);
}

// Pass 2 (PDL secondary): merge replicas, per-group loss_g = log(psum) - S/tsum
// (0 when count<2), global reduce, output write, scratch reset.
// 128 blocks x 256 threads = exactly 1 group/thread; all replica loads independent.
__global__ void k_fin(float* __restrict__ out) {
    asm volatile("griddepcontrol.wait;" ::: "memory");

    int g = blockIdx.x * 256 + threadIdx.x;          // one group per thread
    const float4 Z = make_float4(0.f, 0.f, 0.f, 0.f);
    float4 r0 = __ldcg(&g_acc[0 * NUM_G + g]);
    float4 r1 = __ldcg(&g_acc[1 * NUM_G + g]);
    float4 r2 = __ldcg(&g_acc[2 * NUM_G + g]);
    float4 r3 = __ldcg(&g_acc[3 * NUM_G + g]);
    float4 r4 = __ldcg(&g_acc[4 * NUM_G + g]);
    float4 r5 = __ldcg(&g_acc[5 * NUM_G + g]);
    float4 r6 = __ldcg(&g_acc[6 * NUM_G + g]);
    float4 r7 = __ldcg(&g_acc[7 * NUM_G + g]);
    #pragma unroll
    for (int r = 0; r < NREP; r++) g_acc[r * NUM_G + g] = Z;   // reset for replay

    float4 a;
    a.x = ((r0.x + r1.x) + (r2.x + r3.x)) + ((r4.x + r5.x) + (r6.x + r7.x));
    a.y = ((r0.y + r1.y) + (r2.y + r3.y)) + ((r4.y + r5.y) + (r6.y + r7.y));
    a.z = ((r0.z + r1.z) + (r2.z + r3.z)) + ((r4.z + r5.z) + (r6.z + r7.z));
    a.w = ((r0.w + r1.w) + (r2.w + r3.w)) + ((r4.w + r5.w) + (r6.w + r7.w));

    bool valid = (a.w >= 1.5f);                      // count >= 2
    float s = valid ? (logf(a.y) - a.z / a.x) : 0.0f;
    int c = (int)valid;

    #pragma unroll
    for (int o = 16; o > 0; o >>= 1) {
        s += __shfl_down_sync(0xffffffffu, s, o);
        c += __shfl_down_sync(0xffffffffu, c, o);
    }
    __shared__ float sh[8];
    __shared__ int   shc[8];
    int lane = threadIdx.x & 31, wid = threadIdx.x >> 5;
    if (lane == 0) { sh[wid] = s; shc[wid] = c; }
    __syncthreads();
    if (wid == 0) {
        s = (lane < 8) ? sh[lane] : 0.0f;
        c = (lane < 8) ? shc[lane] : 0;
        #pragma unroll
        for (int o = 4; o > 0; o >>= 1) {
            s += __shfl_down_sync(0xffffffffu, s, o);
            c += __shfl_down_sync(0xffffffffu, c, o);
        }
        if (lane == 0) {
            atomicAdd(&g_total, s);
            atomicAdd(&g_nvalid, c);
            __threadfence();
            unsigned t = atomicAdd(&g_done, 1u);
            if (t == gridDim.x - 1) {
                int   nvg = *(volatile int*)&g_nvalid;
                float tt  = *(volatile float*)&g_total;
                out[0] = (nvg > 0) ? (tt / (float)nvg) : 0.0f;
                g_total = 0.0f; g_nvalid = 0; g_done = 0u;
            }
        }
    }
}

extern "C" void kernel_launch(void* const* d_in, const int* in_sizes, int n_in,
                              void* d_out, int out_size) {
    const float* pred = (const float*)d_in[0];
    const float* targ = (const float*)d_in[1];
    const int*   gid  = (const int*)d_in[2];
    float* out = (float*)d_out;
    int n  = in_sizes[0];
    int nv = n / 4;                       // n is a multiple of 4 (4,194,304)
    int gb = (nv / 2 + 255) / 256;        // 2048 blocks, 8 elements/thread

    k_accum<<<gb, 256>>>((const float4*)pred, (const float4*)targ,
                         (const int4*)gid, nv);

    cudaLaunchConfig_t cfg = {};
    cfg.gridDim  = dim3(128);
    cfg.blockDim = dim3(256);
    cfg.stream   = 0;
    cudaLaunchAttribute attr[1];
    attr[0].id = cudaLaunchAttributeProgrammaticStreamSerialization;
    attr[0].val.programmaticStreamSerializationAllowed = 1;
    cfg.attrs    = attr;
    cfg.numAttrs = 1;
    cudaLaunchKernelEx(&cfg, k_fin, out);
}

// round 16
// speedup vs baseline: 1.0124x; 1.0124x over previous
#include <cuda_runtime.h>
#include <cuda_bf16.h>

#define NUM_G 32768
#define NREP  4      // accumulator replicas (knee found at 4: R14=30.8 vs R15@8=31.2)

// Scratch (allocation-free __device__ globals; zero-initialized at load).
// INVARIANT: all scratch is zero at kernel_launch entry; k_fin restores
// everything to zero, so every graph replay sees identical state.
__device__ float4   g_acc[NREP * NUM_G];  // {tsum, psum, S = sum exp(t)*p, count}
__device__ float    g_total;
__device__ int      g_nvalid;
__device__ unsigned g_done;

// Pure-FMA exp: exp(x) = 2^(x*log2e). Magic-number round, deg-5 poly on [-0.5,0.5].
__device__ __forceinline__ float fexp(float x) {
    const float L2E = 1.4426950408889634f;
    float z  = fmaf(x, L2E, 12582912.0f);
    int   n  = __float_as_int(z) - 0x4B400000;
    float zi = z - 12582912.0f;
    float f  = fmaf(x, L2E, -zi);
    float p  = 1.3333558146e-3f;
    p = fmaf(p, f, 9.6181291076e-3f);
    p = fmaf(p, f, 5.5504108664e-2f);
    p = fmaf(p, f, 2.4022650696e-1f);
    p = fmaf(p, f, 6.9314718056e-1f);
    p = fmaf(p, f, 1.0f);
    return __int_as_float(__float_as_int(p) + (n << 23));
}

// One 16-byte vectorized L2 reduction: {tsum += te, psum += pe, S += te*p, count += 1}
__device__ __forceinline__ void red4(float4* a, float te, float pe, float s) {
    asm volatile("red.global.add.v4.f32 [%0], {%1, %2, %3, %4};"
                 :: "l"(a), "f"(te), "f"(pe), "f"(s), "f"(1.0f) : "memory");
}

// Streaming float4 / int4 loads (evict-first).
__device__ __forceinline__ float4 ldcs4(const float4* p) {
    float4 v;
    asm volatile("ld.global.cs.v4.f32 {%0,%1,%2,%3}, [%4];"
                 : "=f"(v.x), "=f"(v.y), "=f"(v.z), "=f"(v.w) : "l"(p));
    return v;
}
__device__ __forceinline__ int4 ldcs4i(const int4* p) {
    int4 v;
    asm volatile("ld.global.cs.v4.b32 {%0,%1,%2,%3}, [%4];"
                 : "=r"(v.x), "=r"(v.y), "=r"(v.z), "=r"(v.w) : "l"(p));
    return v;
}

// One float4 chunk: 3 loads, 4 fexp, 4 red4 into this block's replica.
__device__ __forceinline__ void accum_chunk(const float4* __restrict__ p4,
                                            const float4* __restrict__ t4,
                                            const int4*  __restrict__ g4,
                                            float4* __restrict__ acc, int i) {
    float4 p = ldcs4(&p4[i]);
    float4 t = ldcs4(&t4[i]);
    int4   g = ldcs4i(&g4[i]);
    float ex = fexp(t.x), ey = fexp(t.y), ez = fexp(t.z), ew = fexp(t.w);
    red4(&acc[g.x], ex, fexp(p.x), ex * p.x);
    red4(&acc[g.y], ey, fexp(p.y), ey * p.y);
    red4(&acc[g.z], ez, fexp(p.z), ez * p.z);
    red4(&acc[g.w], ew, fexp(p.w), ew * p.w);
}

// Pass 1 (identical to R14 best): per-group sums of exp(t), exp(p), exp(t)*p,
// count — ONE red.v4 per element, into one of NREP replicas by blockIdx.
__global__ void __launch_bounds__(256, 8) k_accum(const float4* __restrict__ p4,
                                                  const float4* __restrict__ t4,
                                                  const int4*  __restrict__ g4, int nv) {
    int half = nv >> 1;
    int i = blockIdx.x * blockDim.x + threadIdx.x;
    if (i >= half) return;
    float4* acc = g_acc + ((blockIdx.x & (NREP - 1)) << 15);   // replica base
    accum_chunk(p4, t4, g4, acc, i);
    accum_chunk(p4, t4, g4, acc, i + half);
}

// Pass 2 (PDL secondary): merge replicas, per-group loss_g = log(psum) - S/tsum
// (0 when count<2), global reduce, output write, scratch reset.
// 32 blocks x 256 threads x 4 groups/thread; all 16 replica loads independent
// (deep MLP, one latency shadow) and only 32 closing ticket sequences.
__global__ void k_fin(float* __restrict__ out) {
    asm volatile("griddepcontrol.wait;" ::: "memory");

    int g0 = blockIdx.x * 1024 + threadIdx.x;        // groups: g0 + {0,256,512,768}
    const float4 Z = make_float4(0.f, 0.f, 0.f, 0.f);

    float4 v[4][NREP];
    #pragma unroll
    for (int k = 0; k < 4; k++)
        #pragma unroll
        for (int r = 0; r < NREP; r++)
            v[k][r] = __ldcg(&g_acc[r * NUM_G + g0 + k * 256]);
    #pragma unroll
    for (int k = 0; k < 4; k++)
        #pragma unroll
        for (int r = 0; r < NREP; r++)
            g_acc[r * NUM_G + g0 + k * 256] = Z;     // reset for next replay

    float s = 0.0f;
    int   c = 0;
    #pragma unroll
    for (int k = 0; k < 4; k++) {
        float4 a;
        a.x = (v[k][0].x + v[k][1].x) + (v[k][2].x + v[k][3].x);
        a.y = (v[k][0].y + v[k][1].y) + (v[k][2].y + v[k][3].y);
        a.z = (v[k][0].z + v[k][1].z) + (v[k][2].z + v[k][3].z);
        a.w = (v[k][0].w + v[k][1].w) + (v[k][2].w + v[k][3].w);
        bool valid = (a.w >= 1.5f);                  // count >= 2
        if (valid) s += logf(a.y) - a.z / a.x;
        c += (int)valid;
    }

    #pragma unroll
    for (int o = 16; o > 0; o >>= 1) {
        s += __shfl_down_sync(0xffffffffu, s, o);
        c += __shfl_down_sync(0xffffffffu, c, o);
    }
    __shared__ float sh[8];
    __shared__ int   shc[8];
    int lane = threadIdx.x & 31, wid = threadIdx.x >> 5;
    if (lane == 0) { sh[wid] = s; shc[wid] = c; }
    __syncthreads();
    if (wid == 0) {
        s = (lane < 8) ? sh[lane] : 0.0f;
        c = (lane < 8) ? shc[lane] : 0;
        #pragma unroll
        for (int o = 4; o > 0; o >>= 1) {
            s += __shfl_down_sync(0xffffffffu, s, o);
            c += __shfl_down_sync(0xffffffffu, c, o);
        }
        if (lane == 0) {
            atomicAdd(&g_total, s);
            atomicAdd(&g_nvalid, c);
            __threadfence();
            unsigned t = atomicAdd(&g_done, 1u);
            if (t == gridDim.x - 1) {
                int   nvg = *(volatile int*)&g_nvalid;
                float tt  = *(volatile float*)&g_total;
                out[0] = (nvg > 0) ? (tt / (float)nvg) : 0.0f;
                g_total = 0.0f; g_nvalid = 0; g_done = 0u;
            }
        }
    }
}

extern "C" void kernel_launch(void* const* d_in, const int* in_sizes, int n_in,
                              void* d_out, int out_size) {
    const float* pred = (const float*)d_in[0];
    const float* targ = (const float*)d_in[1];
    const int*   gid  = (const int*)d_in[2];
    float* out = (float*)d_out;
    int n  = in_sizes[0];
    int nv = n / 4;                       // n is a multiple of 4 (4,194,304)
    int gb = (nv / 2 + 255) / 256;        // 2048 blocks, 8 elements/thread

    k_accum<<<gb, 256>>>((const float4*)pred, (const float4*)targ,
                         (const int4*)gid, nv);

    cudaLaunchConfig_t cfg = {};
    cfg.gridDim  = dim3(32);
    cfg.blockDim = dim3(256);
    cfg.stream   = 0;
    cudaLaunchAttribute attr[1];
    attr[0].id = cudaLaunchAttributeProgrammaticStreamSerialization;
    attr[0].val.programmaticStreamSerializationAllowed = 1;
    cfg.attrs    = attr;
    cfg.numAttrs = 1;
    cudaLaunchKernelEx(&cfg, k_fin, out);
}